// round 9
// baseline (speedup 1.0000x reference)
#include <cuda_runtime.h>
#include <cuda_bf16.h>
#include <cstdint>

// Problem constants
#define HIDDEN 2048
#define INTER  1408
#define NEXP   60
#define TOPK   6

#define GU_TILES  (TOPK * INTER)        // 8448 gateup warp-tiles
#define DN_TILES  (TOPK * HIDDEN / 2)   // 6144 down warp-tiles (2 rows each)
#define GU_CHUNKS ((GU_TILES + 7) / 8)  // 1056 block-chunks (8 warps/block)
#define DN_CHUNKS ((DN_TILES + 7) / 8)  // 768
#define GRID      888
#define BLOCK     256

// Persistent device state. All launch-neutral: reset to 0 by the last
// exiting block, so CUDA-graph replays see identical initial state.
__device__ __align__(16) float g_inter[TOPK * INTER]; // 5632B rows = 44 full lines
__device__ unsigned g_cnt[TOPK];
__device__ unsigned gu_ticket, dn_ticket, zero_flag, exit_cnt;

// ---------------------------------------------------------------------------
// Fused persistent MoE kernel.
// Phase A: warp-per-(k,i) gateup GEMV -> g_inter, RED g_cnt[k].
// Phase B: warp-per-(k, h-pair) down GEMV, spinning on g_cnt[k] readiness.
// Ticket work-stealing: a block in phase B implies all gateup tickets are
// held by RUNNING blocks -> progress guaranteed (no residency assumption).
// ---------------------------------------------------------------------------
__global__ __launch_bounds__(BLOCK, 5) void moe_fused_kernel(
    const float* __restrict__ x,
    const void*  __restrict__ idx_raw,
    const float* __restrict__ topk_w,
    const float* __restrict__ gate_up_all,
    const float* __restrict__ down_all,
    float* __restrict__ out)
{
    __shared__ __align__(16) float s_x[HIDDEN];   // 8 KB
    __shared__ int      s_exp[TOPK];
    __shared__ float    s_w[TOPK];
    __shared__ unsigned s_chunk;

    const int tid  = threadIdx.x;
    const int warp = tid >> 5;
    const int lane = tid & 31;

    // Resolve expert indices (int64 per reference; int32 fallback) + weights
    if (tid == 0) {
        const long long* p64 = (const long long*)idx_raw;
        const int*       p32 = (const int*)idx_raw;
        bool ok64 = true;
#pragma unroll
        for (int k = 0; k < TOPK; k++) {
            long long v = p64[k];
            if (v < 0 || v >= NEXP) ok64 = false;
        }
#pragma unroll
        for (int k = 0; k < TOPK; k++) {
            s_exp[k] = ok64 ? (int)p64[k] : p32[k];
            s_w[k]   = topk_w[k];
        }
    }
    // Stage x into smem (512 float4, 2 per thread)
    {
        const float4* src = (const float4*)x;
        float4*       dst = (float4*)s_x;
#pragma unroll
        for (int t = 0; t < HIDDEN / 4 / BLOCK; t++)
            dst[t * BLOCK + tid] = src[t * BLOCK + tid];
    }
    __syncthreads();

    // ---------------- Phase A: gateup ----------------
    for (;;) {
        if (tid == 0) s_chunk = atomicAdd(&gu_ticket, 1u);
        __syncthreads();
        unsigned c = s_chunk;
        if (c >= GU_CHUNKS) break;

        if (c == 0) {
            // First chunk also zeroes the output (once per launch)
#pragma unroll
            for (int t = 0; t < HIDDEN / BLOCK; t++)
                out[t * BLOCK + tid] = 0.f;
            __threadfence();
            if (tid == 0) atomicExch(&zero_flag, 1u);
        }

        unsigned t = c * 8 + warp;
        if (t < GU_TILES) {
            int k = t / INTER;
            int i = t - k * INTER;
            int e = s_exp[k];
            const float4* xv4  = (const float4*)s_x;
            const float4* grow = (const float4*)(gate_up_all + ((size_t)e * (2 * INTER) + i) * HIDDEN);
            const float4* urow = (const float4*)(gate_up_all + ((size_t)e * (2 * INTER) + INTER + i) * HIDDEN);

            float dg = 0.f, du = 0.f;
#pragma unroll
            for (int tt = 0; tt < HIDDEN / 128; tt++) {   // 16 iters
                int idx = tt * 32 + lane;
                float4 xv = xv4[idx];
                float4 gv = __ldcs(grow + idx);
                float4 uv = __ldcs(urow + idx);
                dg += xv.x * gv.x + xv.y * gv.y + xv.z * gv.z + xv.w * gv.w;
                du += xv.x * uv.x + xv.y * uv.y + xv.z * uv.z + xv.w * uv.w;
            }
#pragma unroll
            for (int o = 16; o; o >>= 1) {
                dg += __shfl_xor_sync(0xffffffffu, dg, o);
                du += __shfl_xor_sync(0xffffffffu, du, o);
            }
            if (lane == 0) {
                float s = dg / (1.f + __expf(-dg));
                g_inter[t] = s * du * s_w[k];
                __threadfence();                 // publish before counting
                atomicAdd(&g_cnt[k], 1u);        // fire-and-forget RED
            }
        }
    }

    // ---------------- Phase B: down ----------------
    if (tid == 0) {
        while (((volatile unsigned*)&zero_flag)[0] == 0u) __nanosleep(64);
    }
    __syncthreads();

    for (;;) {
        if (tid == 0) s_chunk = atomicAdd(&dn_ticket, 1u);
        __syncthreads();
        unsigned c = s_chunk;
        if (c >= DN_CHUNKS) break;

        unsigned t = c * 8 + warp;
        if (t < DN_TILES) {
            int k  = t >> 10;                 // / (HIDDEN/2)
            int h0 = (int)(t & 1023) << 1;

            if (lane == 0) {
                while (((volatile unsigned*)g_cnt)[k] < (unsigned)INTER) __nanosleep(64);
            }
            __syncwarp();
            __threadfence();                  // acquire g_inter[k,:]

            int e = s_exp[k];
            const float4* row0 = (const float4*)(down_all + ((size_t)e * HIDDEN + h0) * INTER);
            const float4* row1 = row0 + INTER / 4;
            const float4* iv   = (const float4*)(g_inter + k * INTER);

            float acc0 = 0.f, acc1 = 0.f;
#pragma unroll
            for (int tt = 0; tt < INTER / 128; tt++) {   // 11 iters
                int idx = tt * 32 + lane;
                float4 a0 = __ldcs(row0 + idx);
                float4 a1 = __ldcs(row1 + idx);
                float4 b  = __ldg (iv   + idx);
                acc0 += a0.x * b.x + a0.y * b.y + a0.z * b.z + a0.w * b.w;
                acc1 += a1.x * b.x + a1.y * b.y + a1.z * b.z + a1.w * b.w;
            }
#pragma unroll
            for (int o = 16; o; o >>= 1) {
                acc0 += __shfl_xor_sync(0xffffffffu, acc0, o);
                acc1 += __shfl_xor_sync(0xffffffffu, acc1, o);
            }
            if (lane == 0) {
                atomicAdd(out + h0,     acc0);
                atomicAdd(out + h0 + 1, acc1);
            }
        }
    }

    // ---------------- Exit & reset (graph-replay hygiene) ----------------
    __syncthreads();
    if (tid == 0) {
        unsigned e = atomicAdd(&exit_cnt, 1u);
        if (e == GRID - 1) {
            // Last block out: every other block has taken its final tickets
            // and performs no further global ops. Safe to reset.
            gu_ticket = 0; dn_ticket = 0; zero_flag = 0;
#pragma unroll
            for (int k = 0; k < TOPK; k++) g_cnt[k] = 0;
            __threadfence();
            exit_cnt = 0;
            __threadfence();
        }
    }
}

// ---------------------------------------------------------------------------
// Inputs (metadata order):
//   0: x_bc1t        float32 [2048]
//   1: topk_idx      int64   [6]
//   2: topk_weights  float32 [6]
//   3: gate_up_all   float32 [60, 2816, 2048]
//   4: down_all      float32 [60, 2048, 1408]
// Output: float32 [2048]
// ---------------------------------------------------------------------------
extern "C" void kernel_launch(void* const* d_in, const int* in_sizes, int n_in,
                              void* d_out, int out_size) {
    const float* x    = (const float*)d_in[0];
    const void*  idx  = d_in[1];
    const float* w    = (const float*)d_in[2];
    const float* gu   = (const float*)d_in[3];
    const float* down = (const float*)d_in[4];
    float*       out  = (float*)d_out;

    moe_fused_kernel<<<GRID, BLOCK>>>(x, idx, w, gu, down, out);
}

// round 10
// speedup vs baseline: 1.3151x; 1.3151x over previous
#include <cuda_runtime.h>
#include <cuda_bf16.h>
#include <cstdint>

// Problem constants
#define HIDDEN 2048
#define INTER  1408
#define NEXP   60
#define TOPK   6

// Scratch (no cudaMalloc allowed)
__device__ __align__(16) float g_inter[TOPK * INTER]; // weighted silu(gate)*up

// ---------------------------------------------------------------------------
// Warp-local expert resolve: no shared memory, no __syncthreads.
// Lane l (<6) inspects idx[l]; ballot decides int64 vs int32; shfl broadcasts.
// Returns expert id for slot k. The 48B of idx is L1-hot after first touch.
// ---------------------------------------------------------------------------
__device__ __forceinline__ int warp_expert(const void* idx_raw, int k, int lane) {
    const long long* p64 = (const long long*)idx_raw;
    const int*       p32 = (const int*)idx_raw;
    long long v64 = 0; int v32 = 0;
    if (lane < TOPK) { v64 = __ldg(p64 + lane); v32 = __ldg(p32 + lane); }
    unsigned good = __ballot_sync(0xffffffffu, lane < TOPK && v64 >= 0 && v64 < NEXP);
    bool ok64 = (good & 0x3Fu) == 0x3Fu;
    int e = ok64 ? (int)v64 : v32;
    return __shfl_sync(0xffffffffu, e, k);
}

// ---------------------------------------------------------------------------
// Kernel 1: warp per (k,i):
//   g = dot(gate_row, x), u = dot(up_row, x)
//   g_inter[k*INTER+i] = silu(g) * u * topk_weights[k]
// 128-thread blocks (2112) for fine wave granularity; x via __ldg (8KB,
// L1-resident). Block 0 zeroes `out` for down's atomics. No block syncs.
// ---------------------------------------------------------------------------
__global__ __launch_bounds__(128) void gateup_kernel(
    const float* __restrict__ x,
    const void*  __restrict__ idx_raw,
    const float* __restrict__ topk_w,
    const float* __restrict__ gate_up_all,
    float* __restrict__ out)
{
    int warp  = threadIdx.x >> 5;
    int lane  = threadIdx.x & 31;
    int gwarp = blockIdx.x * 4 + warp;

    // Block 0 zeroes the output (down_kernel accumulates with atomics)
    if (blockIdx.x == 0) {
#pragma unroll
        for (int t = 0; t < HIDDEN / 128; t++)
            out[t * 128 + threadIdx.x] = 0.f;
    }

    if (gwarp >= TOPK * INTER) return;

    int k = gwarp / INTER;
    int i = gwarp - k * INTER;
    int e = warp_expert(idx_raw, k, lane);

    const float4* xv4  = (const float4*)x;
    const float4* grow = (const float4*)(gate_up_all + ((size_t)e * (2 * INTER) + i) * HIDDEN);
    const float4* urow = (const float4*)(gate_up_all + ((size_t)e * (2 * INTER) + INTER + i) * HIDDEN);

    float dg = 0.f, du = 0.f;
#pragma unroll
    for (int t = 0; t < HIDDEN / 128; t++) {      // 16 iterations
        int idx = t * 32 + lane;
        float4 xv = __ldg (xv4  + idx);           // L1-hot
        float4 gv = __ldcs(grow + idx);           // stream-once
        float4 uv = __ldcs(urow + idx);
        dg += xv.x * gv.x + xv.y * gv.y + xv.z * gv.z + xv.w * gv.w;
        du += xv.x * uv.x + xv.y * uv.y + xv.z * uv.z + xv.w * uv.w;
    }
#pragma unroll
    for (int o = 16; o; o >>= 1) {
        dg += __shfl_xor_sync(0xffffffffu, dg, o);
        du += __shfl_xor_sync(0xffffffffu, du, o);
    }
    if (lane == 0) {
        float s = dg / (1.f + __expf(-dg));        // silu
        g_inter[gwarp] = s * du * __ldg(topk_w + k);
    }
}

// ---------------------------------------------------------------------------
// Kernel 2: warp per (k, h-pair): two adjacent rows h0, h0+1 of expert k
// (contiguous in DRAM -> 2 independent streams/warp, proven best shape).
// 128-thread blocks (1536) for fine waves; warp-local resolve, no syncs:
// each warp issues its first DRAM load immediately.
// ---------------------------------------------------------------------------
__global__ __launch_bounds__(128) void down_kernel(
    const void*  __restrict__ idx_raw,
    const float* __restrict__ down_all,
    float* __restrict__ out)
{
    int warp  = threadIdx.x >> 5;
    int lane  = threadIdx.x & 31;
    int gwarp = blockIdx.x * 4 + warp;        // 0 .. 6143
    if (gwarp >= TOPK * HIDDEN / 2) return;

    int k  = gwarp >> 10;                     // / (HIDDEN/2)
    int h0 = (gwarp & (HIDDEN / 2 - 1)) << 1; // even row
    int e  = warp_expert(idx_raw, k, lane);

    const float4* row0 = (const float4*)(down_all + ((size_t)e * HIDDEN + h0) * INTER);
    const float4* row1 = row0 + INTER / 4;    // contiguous next row
    const float4* iv   = (const float4*)(g_inter + k * INTER);

    float acc0 = 0.f, acc1 = 0.f;
#pragma unroll
    for (int t = 0; t < INTER / 128; t++) {       // 11 iterations
        int idx = t * 32 + lane;
        float4 a0 = __ldcs(row0 + idx);           // stream 0
        float4 a1 = __ldcs(row1 + idx);           // stream 1
        float4 b  = __ldg (iv   + idx);           // L1/L2-hot
        acc0 += a0.x * b.x + a0.y * b.y + a0.z * b.z + a0.w * b.w;
        acc1 += a1.x * b.x + a1.y * b.y + a1.z * b.z + a1.w * b.w;
    }
#pragma unroll
    for (int o = 16; o; o >>= 1) {
        acc0 += __shfl_xor_sync(0xffffffffu, acc0, o);
        acc1 += __shfl_xor_sync(0xffffffffu, acc1, o);
    }
    if (lane == 0) {
        atomicAdd(out + h0,     acc0);
        atomicAdd(out + h0 + 1, acc1);
    }
}

// ---------------------------------------------------------------------------
// Inputs (metadata order):
//   0: x_bc1t        float32 [2048]
//   1: topk_idx      int64   [6]
//   2: topk_weights  float32 [6]
//   3: gate_up_all   float32 [60, 2816, 2048]
//   4: down_all      float32 [60, 2048, 1408]
// Output: float32 [2048]
// ---------------------------------------------------------------------------
extern "C" void kernel_launch(void* const* d_in, const int* in_sizes, int n_in,
                              void* d_out, int out_size) {
    const float* x    = (const float*)d_in[0];
    const void*  idx  = d_in[1];
    const float* w    = (const float*)d_in[2];
    const float* gu   = (const float*)d_in[3];
    const float* down = (const float*)d_in[4];
    float*       out  = (float*)d_out;

    int blocks1 = (TOPK * INTER + 3) / 4;        // 2112 blocks x 128 thr
    gateup_kernel<<<blocks1, 128>>>(x, idx, w, gu, out);

    int blocks2 = (TOPK * HIDDEN / 2 + 3) / 4;   // 1536 blocks x 128 thr
    down_kernel<<<blocks2, 128>>>(idx, down, out);
}

// round 12
// speedup vs baseline: 1.3674x; 1.0397x over previous
#include <cuda_runtime.h>
#include <cuda_bf16.h>
#include <cstdint>

// Problem constants
#define HIDDEN 2048
#define INTER  1408
#define NEXP   60
#define TOPK   6

// Scratch (no cudaMalloc allowed)
__device__ __align__(16) float g_inter[TOPK * INTER]; // weighted silu(gate)*up

// ---------------------------------------------------------------------------
// Warp-local expert resolve: no shared memory, no __syncthreads.
// Lane l (<6) inspects idx[l]; ballot decides int64 vs int32; shfl broadcasts.
// ---------------------------------------------------------------------------
__device__ __forceinline__ int warp_expert(const void* idx_raw, int k, int lane) {
    const long long* p64 = (const long long*)idx_raw;
    const int*       p32 = (const int*)idx_raw;
    long long v64 = 0; int v32 = 0;
    if (lane < TOPK) { v64 = __ldg(p64 + lane); v32 = __ldg(p32 + lane); }
    unsigned good = __ballot_sync(0xffffffffu, lane < TOPK && v64 >= 0 && v64 < NEXP);
    bool ok64 = (good & 0x3Fu) == 0x3Fu;
    int e = ok64 ? (int)v64 : v32;
    return __shfl_sync(0xffffffffu, e, k);
}

// ---------------------------------------------------------------------------
// Kernel 1: warp per (k,i):
//   g = dot(gate_row, x), u = dot(up_row, x)
//   g_inter[k*INTER+i] = silu(g) * u * topk_weights[k]
// 2112 blocks x 128 thr; x via __ldg (8KB, L1-resident). Block 0 zeroes out.
// ---------------------------------------------------------------------------
__global__ __launch_bounds__(128) void gateup_kernel(
    const float* __restrict__ x,
    const void*  __restrict__ idx_raw,
    const float* __restrict__ topk_w,
    const float* __restrict__ gate_up_all,
    float* __restrict__ out)
{
    int warp  = threadIdx.x >> 5;
    int lane  = threadIdx.x & 31;
    int gwarp = blockIdx.x * 4 + warp;

    // Block 0 zeroes the output (down_kernel accumulates with atomics)
    if (blockIdx.x == 0) {
#pragma unroll
        for (int t = 0; t < HIDDEN / 128; t++)
            out[t * 128 + threadIdx.x] = 0.f;
    }

    if (gwarp >= TOPK * INTER) return;

    int k = gwarp / INTER;
    int i = gwarp - k * INTER;
    int e = warp_expert(idx_raw, k, lane);

    const float4* xv4  = (const float4*)x;
    const float4* grow = (const float4*)(gate_up_all + ((size_t)e * (2 * INTER) + i) * HIDDEN);
    const float4* urow = (const float4*)(gate_up_all + ((size_t)e * (2 * INTER) + INTER + i) * HIDDEN);

    float dg = 0.f, du = 0.f;
#pragma unroll
    for (int t = 0; t < HIDDEN / 128; t++) {      // 16 iterations
        int idx = t * 32 + lane;
        float4 xv = __ldg (xv4  + idx);           // L1-hot
        float4 gv = __ldcs(grow + idx);           // stream-once
        float4 uv = __ldcs(urow + idx);
        dg += xv.x * gv.x + xv.y * gv.y + xv.z * gv.z + xv.w * gv.w;
        du += xv.x * uv.x + xv.y * uv.y + xv.z * uv.z + xv.w * uv.w;
    }
#pragma unroll
    for (int o = 16; o; o >>= 1) {
        dg += __shfl_xor_sync(0xffffffffu, dg, o);
        du += __shfl_xor_sync(0xffffffffu, du, o);
    }
    if (lane == 0) {
        float s = dg / (1.f + __expf(-dg));        // silu
        g_inter[gwarp] = s * du * __ldg(topk_w + k);
    }
}

// ---------------------------------------------------------------------------
// Kernel 2: warp per (k, h-pair, half). Each warp handles the SAME two
// contiguous rows h0,h0+1 of expert k but only half the dot-product
// iterations: half 0 -> t=0..5, half 1 -> t=6..10. 12288 warps (~full
// occupancy), short fully-batchable load streams, proven 2-stream shape.
// down is linear (silu already folded into g_inter) so partials combine
// via atomicAdd (REDG; 12 partials per address, negligible).
// ---------------------------------------------------------------------------
__global__ __launch_bounds__(128) void down_kernel(
    const void*  __restrict__ idx_raw,
    const float* __restrict__ down_all,
    float* __restrict__ out)
{
    int warp  = threadIdx.x >> 5;
    int lane  = threadIdx.x & 31;
    int gwarp = blockIdx.x * 4 + warp;        // 0 .. 12287
    if (gwarp >= TOPK * HIDDEN) return;       // TOPK*HIDDEN/2 pairs * 2 halves

    int pair = gwarp >> 1;
    int half = gwarp & 1;
    int k    = pair >> 10;                    // / (HIDDEN/2)
    int h0   = (pair & (HIDDEN / 2 - 1)) << 1;
    int e    = warp_expert(idx_raw, k, lane);

    const float4* row0 = (const float4*)(down_all + ((size_t)e * HIDDEN + h0) * INTER);
    const float4* row1 = row0 + INTER / 4;    // contiguous next row
    const float4* iv   = (const float4*)(g_inter + k * INTER);

    int base = half * 6;                      // half0: t=0..5, half1: t=6..10

    float acc0 = 0.f, acc1 = 0.f;
#pragma unroll
    for (int tt = 0; tt < 5; tt++) {          // 5 common iterations
        int idx = (base + tt) * 32 + lane;
        float4 a0 = __ldcs(row0 + idx);
        float4 a1 = __ldcs(row1 + idx);
        float4 b  = __ldg (iv   + idx);
        acc0 += a0.x * b.x + a0.y * b.y + a0.z * b.z + a0.w * b.w;
        acc1 += a1.x * b.x + a1.y * b.y + a1.z * b.z + a1.w * b.w;
    }
    if (half == 0) {                          // extra iteration t=5
        int idx = 5 * 32 + lane;
        float4 a0 = __ldcs(row0 + idx);
        float4 a1 = __ldcs(row1 + idx);
        float4 b  = __ldg (iv   + idx);
        acc0 += a0.x * b.x + a0.y * b.y + a0.z * b.z + a0.w * b.w;
        acc1 += a1.x * b.x + a1.y * b.y + a1.z * b.z + a1.w * b.w;
    }
#pragma unroll
    for (int o = 16; o; o >>= 1) {
        acc0 += __shfl_xor_sync(0xffffffffu, acc0, o);
        acc1 += __shfl_xor_sync(0xffffffffu, acc1, o);
    }
    if (lane == 0) {
        atomicAdd(out + h0,     acc0);
        atomicAdd(out + h0 + 1, acc1);
    }
}

// ---------------------------------------------------------------------------
// Inputs (metadata order):
//   0: x_bc1t        float32 [2048]
//   1: topk_idx      int64   [6]
//   2: topk_weights  float32 [6]
//   3: gate_up_all   float32 [60, 2816, 2048]
//   4: down_all      float32 [60, 2048, 1408]
// Output: float32 [2048]
// ---------------------------------------------------------------------------
extern "C" void kernel_launch(void* const* d_in, const int* in_sizes, int n_in,
                              void* d_out, int out_size) {
    const float* x    = (const float*)d_in[0];
    const void*  idx  = d_in[1];
    const float* w    = (const float*)d_in[2];
    const float* gu   = (const float*)d_in[3];
    const float* down = (const float*)d_in[4];
    float*       out  = (float*)d_out;

    int blocks1 = (TOPK * INTER + 3) / 4;        // 2112 blocks x 128 thr
    gateup_kernel<<<blocks1, 128>>>(x, idx, w, gu, out);

    int blocks2 = (TOPK * HIDDEN + 3) / 4;       // 3072 blocks x 128 thr
    down_kernel<<<blocks2, 128>>>(idx, down, out);
}